// round 1
// baseline (speedup 1.0000x reference)
#include <cuda_runtime.h>
#include <cstddef>

#define N_NODES 100000
#define N_EDGES 1600000
#define F_IN    128
#define HID     150
#define HID_PAD 160
#define N_OUT   128
#define W1_ROWS 256   // 128 self + 128 neigh
#define W1_COLS 192   // 150 padded to 3*64

// ---------------- scratch (static device globals; zero-initialized) ----------
__device__ float g_deg[N_NODES];
__device__ float g_deginv[N_NODES];
__device__ float g_agg1[(size_t)N_NODES * F_IN];
__device__ float g_agg2[(size_t)N_NODES * N_OUT];
__device__ float g_h1[(size_t)N_NODES * HID_PAD];   // cols 150..159 stay 0 forever
__device__ float g_t2[(size_t)N_NODES * N_OUT];
__device__ float g_W1cat[W1_ROWS * W1_COLS];
__device__ float g_W2s[HID_PAD * N_OUT];
__device__ float g_W2n[HID_PAD * N_OUT];

// ---------------- small utility kernels --------------------------------------
__global__ void zero_f4(float4* p, size_t n4) {
    size_t i = (size_t)blockIdx.x * blockDim.x + threadIdx.x;
    size_t stride = (size_t)gridDim.x * blockDim.x;
    float4 z = make_float4(0.f, 0.f, 0.f, 0.f);
    for (; i < n4; i += stride) p[i] = z;
}

__global__ void prep_weights(const float* __restrict__ Ws1,
                             const float* __restrict__ Wn1,
                             const float* __restrict__ Ws2,
                             const float* __restrict__ Wn2) {
    int i = blockIdx.x * blockDim.x + threadIdx.x;
    if (i < W1_ROWS * W1_COLS) {
        int k = i / W1_COLS, n = i % W1_COLS;
        float v = 0.f;
        if (n < HID) v = (k < F_IN) ? Ws1[k * HID + n] : Wn1[(k - F_IN) * HID + n];
        g_W1cat[i] = v;
    }
    if (i < HID_PAD * N_OUT) {
        int k = i / N_OUT, n = i % N_OUT;
        g_W2s[i] = (k < HID) ? Ws2[k * N_OUT + n] : 0.f;
        g_W2n[i] = (k < HID) ? Wn2[k * N_OUT + n] : 0.f;
    }
}

__global__ void deg_kernel(const int* __restrict__ dst) {
    int e = blockIdx.x * blockDim.x + threadIdx.x;
    if (e < N_EDGES) atomicAdd(&g_deg[dst[e]], 1.0f);
}

__global__ void deginv_kernel() {
    int i = blockIdx.x * blockDim.x + threadIdx.x;
    if (i < N_NODES) {
        float d = g_deg[i];
        g_deginv[i] = (d > 0.f) ? (1.0f / d) : 0.f;
    }
}

// one warp per edge; 32 lanes * float4 = 128 features
__global__ void scatter128(const float* __restrict__ feat,
                           const int* __restrict__ src,
                           const int* __restrict__ dst,
                           float* __restrict__ out) {
    long long gid = (long long)blockIdx.x * blockDim.x + threadIdx.x;
    int e = (int)(gid >> 5);
    int lane = (int)(gid & 31);
    if (e >= N_EDGES) return;
    int s = __ldg(&src[e]);
    int d = __ldg(&dst[e]);
    float4 v = ((const float4*)feat)[(size_t)s * 32 + lane];
    float* p = out + (size_t)d * 128 + lane * 4;
    asm volatile("red.global.add.v4.f32 [%0], {%1, %2, %3, %4};"
                 :: "l"(p), "f"(v.x), "f"(v.y), "f"(v.z), "f"(v.w) : "memory");
}

// ---------------- fused GEMM ---------------------------------------------------
// MODE 1: C = relu([A | deginv*A2] @ W + bias)       A=x(lda 128), A2=agg1, K=256
// MODE 2: C = A @ W                                  A=h1(lda 160), K=160
// MODE 3: C = A @ W + bias + deginv[row]*addin[row,col]
template <int MODE>
__global__ void __launch_bounds__(256)
gemm_kernel(const float* __restrict__ A,
            const float* __restrict__ A2,
            const float* __restrict__ W,
            const float* __restrict__ bias,
            const float* __restrict__ addin,
            float* __restrict__ C,
            int M, int Nstore, int K, int lda, int ldw, int ldc) {
    __shared__ float As[16][68];
    __shared__ float Bs[16][64];
    __shared__ float dvs[64];

    int tid = threadIdx.x;
    int row0 = blockIdx.y * 64;
    int n0 = blockIdx.x * 64;

    if (MODE == 1 || MODE == 3) {
        if (tid < 64) {
            int r = row0 + tid;
            dvs[tid] = (r < M) ? g_deginv[r] : 0.f;
        }
    }

    int ty = tid >> 4, tx = tid & 15;
    int am = tid >> 2;           // 0..63 (row within tile)
    int ak = (tid & 3) * 4;      // 0,4,8,12
    int bk = tid >> 4;           // 0..15
    int bn = (tid & 15) * 4;     // 0..60

    float acc[4][4];
#pragma unroll
    for (int i = 0; i < 4; i++)
#pragma unroll
        for (int j = 0; j < 4; j++) acc[i][j] = 0.f;

    for (int k0 = 0; k0 < K; k0 += 16) {
        // global loads into registers
        float4 av = make_float4(0.f, 0.f, 0.f, 0.f);
        int row = row0 + am;
        if (row < M) {
            if (MODE == 1) {
                if (k0 < 128) {
                    av = *(const float4*)&A[(size_t)row * 128 + k0 + ak];
                } else {
                    av = *(const float4*)&A2[(size_t)row * 128 + (k0 - 128) + ak];
                }
            } else {
                av = *(const float4*)&A[(size_t)row * lda + k0 + ak];
            }
        }
        float4 bv = *(const float4*)&W[(size_t)(k0 + bk) * ldw + n0 + bn];

        __syncthreads();   // previous compute done (also guards dvs on 1st iter)
        if (MODE == 1 && k0 >= 128) {
            float dv = dvs[am];
            av.x *= dv; av.y *= dv; av.z *= dv; av.w *= dv;
        }
        As[ak + 0][am] = av.x;
        As[ak + 1][am] = av.y;
        As[ak + 2][am] = av.z;
        As[ak + 3][am] = av.w;
        *(float4*)&Bs[bk][bn] = bv;
        __syncthreads();

#pragma unroll
        for (int kk = 0; kk < 16; kk++) {
            float4 a = *(const float4*)&As[kk][ty * 4];
            float4 b = *(const float4*)&Bs[kk][tx * 4];
            float ar[4] = {a.x, a.y, a.z, a.w};
            float br[4] = {b.x, b.y, b.z, b.w};
#pragma unroll
            for (int i = 0; i < 4; i++)
#pragma unroll
                for (int j = 0; j < 4; j++)
                    acc[i][j] = fmaf(ar[i], br[j], acc[i][j]);
        }
    }

    // epilogue
#pragma unroll
    for (int i = 0; i < 4; i++) {
        int row = row0 + ty * 4 + i;
        if (row >= M) continue;
#pragma unroll
        for (int j = 0; j < 4; j++) {
            int col = n0 + tx * 4 + j;
            if (col >= Nstore) continue;
            float v = acc[i][j];
            if (MODE == 1) {
                v += bias[col];
                v = fmaxf(v, 0.f);
            }
            if (MODE == 3) {
                v += bias[col] + dvs[ty * 4 + i] * addin[(size_t)row * 128 + col];
            }
            C[(size_t)row * ldc + col] = v;
        }
    }
}

// ---------------- launch --------------------------------------------------------
extern "C" void kernel_launch(void* const* d_in, const int* in_sizes, int n_in,
                              void* d_out, int out_size) {
    const float* x   = (const float*)d_in[0];
    const int*   src = (const int*)d_in[1];
    const int*   dst = (const int*)d_in[2];
    const float* Ws1 = (const float*)d_in[3];
    const float* Wn1 = (const float*)d_in[4];
    const float* b1  = (const float*)d_in[5];
    const float* Ws2 = (const float*)d_in[6];
    const float* Wn2 = (const float*)d_in[7];
    const float* b2  = (const float*)d_in[8];
    float* out = (float*)d_out;

    float *p_deg, *p_agg1, *p_agg2, *p_h1, *p_t2, *p_W1, *p_W2s, *p_W2n;
    cudaGetSymbolAddress((void**)&p_deg,  g_deg);
    cudaGetSymbolAddress((void**)&p_agg1, g_agg1);
    cudaGetSymbolAddress((void**)&p_agg2, g_agg2);
    cudaGetSymbolAddress((void**)&p_h1,   g_h1);
    cudaGetSymbolAddress((void**)&p_t2,   g_t2);
    cudaGetSymbolAddress((void**)&p_W1,   g_W1cat);
    cudaGetSymbolAddress((void**)&p_W2s,  g_W2s);
    cudaGetSymbolAddress((void**)&p_W2n,  g_W2n);

    // 1) zero deg + agg buffers
    zero_f4<<<128, 256>>>((float4*)p_deg, (size_t)N_NODES / 4);
    zero_f4<<<2048, 256>>>((float4*)p_agg1, (size_t)N_NODES * F_IN / 4);
    zero_f4<<<2048, 256>>>((float4*)p_agg2, (size_t)N_NODES * N_OUT / 4);

    // 2) padded/concatenated weights
    prep_weights<<<(W1_ROWS * W1_COLS + 255) / 256, 256>>>(Ws1, Wn1, Ws2, Wn2);

    // 3) degree + inverse
    deg_kernel<<<(N_EDGES + 255) / 256, 256>>>(dst);
    deginv_kernel<<<(N_NODES + 255) / 256, 256>>>();

    // 4) scatter x into agg1
    {
        long long threads = (long long)N_EDGES * 32;
        int blocks = (int)((threads + 255) / 256);
        scatter128<<<blocks, 256>>>(x, src, dst, p_agg1);
    }

    // 5) layer 1 fused GEMM -> h1 (relu)
    {
        dim3 grid(3, (N_NODES + 63) / 64);
        gemm_kernel<1><<<grid, 256>>>(x, p_agg1, p_W1, b1, nullptr, p_h1,
                                      N_NODES, HID, W1_ROWS, 128, W1_COLS, HID_PAD);
    }

    // 6) t2 = h1 @ W_neigh2
    {
        dim3 grid(2, (N_NODES + 63) / 64);
        gemm_kernel<2><<<grid, 256>>>(p_h1, nullptr, p_W2n, nullptr, nullptr, p_t2,
                                      N_NODES, N_OUT, HID_PAD, HID_PAD, N_OUT, N_OUT);
    }

    // 7) scatter t2 into agg2
    {
        long long threads = (long long)N_EDGES * 32;
        int blocks = (int)((threads + 255) / 256);
        scatter128<<<blocks, 256>>>(p_t2, src, dst, p_agg2);
    }

    // 8) out = h1 @ W_self2 + b2 + deginv*agg2
    {
        dim3 grid(2, (N_NODES + 63) / 64);
        gemm_kernel<3><<<grid, 256>>>(p_h1, nullptr, p_W2s, b2, p_agg2, out,
                                      N_NODES, N_OUT, HID_PAD, HID_PAD, N_OUT, N_OUT);
    }
}